// round 14
// baseline (speedup 1.0000x reference)
#include <cuda_runtime.h>
#include <cuda_bf16.h>
#include <cuda_fp16.h>

#define NN 50000
#define EE 800000
#define FIN 128
#define HH 8
#define CC 32
#define HC 256
#define SCAN_NB 196            // ceil(50000/256)

__device__ __half g_hh[NN * HC];      // h in fp16 (gather payload)
__device__ float g_asrc[NN * HH];
__device__ float g_adst[NN * HH];
__device__ int   g_deg[NN];
__device__ int   g_rowptr[NN + 1];
__device__ int2  g_edge[EE];          // (src, eid) packed
__device__ int   g_bsum[SCAN_NB];
__device__ int   g_bbase[SCAN_NB];
__device__ int   g_is64;

// ---------------- init: zero degree counters + detect edge_index dtype --------
__global__ void init_kernel(const void* ei, int n) {
    int i = blockIdx.x * blockDim.x + threadIdx.x;
    if (i < n) g_deg[i] = 0;
    if (i == 0) {
        const long long* p = (const long long*)ei;
        int ok = 1;
        for (int k = 0; k < 16; k++) {
            long long v = p[k];
            if (v < 0 || v >= NN) ok = 0;
        }
        g_is64 = ok;
    }
}

__device__ __forceinline__ int edge_idx(const void* ei, long long k, int is64) {
    return is64 ? (int)((const long long*)ei)[k] : ((const int*)ei)[k];
}

// ---------- tensor-core GEMM: 128Mx64N per block, full K=128 in smem ----------
// (R13 configuration — measured 37.0us; unchanged)
__global__ __launch_bounds__(256, 1)
void gemm_kernel(const float* __restrict__ A, const float* __restrict__ B,
                 const float* __restrict__ att_src, const float* __restrict__ att_dst,
                 int M) {
    __shared__ __align__(16) unsigned char sm[49152];
    const int tid = threadIdx.x;
    const int lane = tid & 31, w = tid >> 5;
    const int bm = blockIdx.x * 128;
    const int bn = blockIdx.y * 64;

    #pragma unroll
    for (int j = 0; j < 8; j++) {
        const int ci = j * 256 + tid;
        const int m = ci >> 4, kc = ci & 15;
        uint4 v = make_uint4(0u, 0u, 0u, 0u);
        if (bm + m < M) {
            const float4 f0 = *(const float4*)&A[(size_t)(bm + m) * FIN + kc * 8];
            const float4 f1 = *(const float4*)&A[(size_t)(bm + m) * FIN + kc * 8 + 4];
            __half2 h0 = __floats2half2_rn(f0.x, f0.y);
            __half2 h1 = __floats2half2_rn(f0.z, f0.w);
            __half2 h2 = __floats2half2_rn(f1.x, f1.y);
            __half2 h3 = __floats2half2_rn(f1.z, f1.w);
            v = make_uint4(*(unsigned*)&h0, *(unsigned*)&h1,
                           *(unsigned*)&h2, *(unsigned*)&h3);
        }
        *(uint4*)&sm[m * 256 + ((kc ^ (m & 7)) << 4)] = v;
    }
    #pragma unroll
    for (int j = 0; j < 4; j++) {
        const int ci = j * 256 + tid;
        const int k = ci >> 3, nc = ci & 7;
        const float4 f0 = *(const float4*)&B[(size_t)k * HC + bn + nc * 8];
        const float4 f1 = *(const float4*)&B[(size_t)k * HC + bn + nc * 8 + 4];
        __half2 h0 = __floats2half2_rn(f0.x, f0.y);
        __half2 h1 = __floats2half2_rn(f0.z, f0.w);
        __half2 h2 = __floats2half2_rn(f1.x, f1.y);
        __half2 h3 = __floats2half2_rn(f1.z, f1.w);
        uint4 v = make_uint4(*(unsigned*)&h0, *(unsigned*)&h1,
                             *(unsigned*)&h2, *(unsigned*)&h3);
        *(uint4*)&sm[32768 + k * 128 + ((nc ^ (k & 7)) << 4)] = v;
    }
    __syncthreads();

    const int wm = (w & 3) * 32;
    const int wn = (w >> 2) * 32;
    const unsigned smb = (unsigned)__cvta_generic_to_shared(sm);

    float c[2][4][4];
    #pragma unroll
    for (int mi = 0; mi < 2; mi++)
        #pragma unroll
        for (int ni = 0; ni < 4; ni++)
            #pragma unroll
            for (int q = 0; q < 4; q++) c[mi][ni][q] = 0.f;

    #pragma unroll
    for (int ks = 0; ks < 8; ks++) {
        unsigned ra[2][4];
        #pragma unroll
        for (int mi = 0; mi < 2; mi++) {
            const int row = wm + mi * 16 + (lane & 15);
            const int kc = ks * 2 + (lane >> 4);
            const unsigned addr = smb + row * 256 + ((kc ^ (row & 7)) << 4);
            asm volatile("ldmatrix.sync.aligned.m8n8.x4.shared.b16 {%0,%1,%2,%3}, [%4];"
                : "=r"(ra[mi][0]), "=r"(ra[mi][1]), "=r"(ra[mi][2]), "=r"(ra[mi][3])
                : "r"(addr));
        }
        unsigned rb[4][2];
        #pragma unroll
        for (int ni = 0; ni < 4; ni++) {
            const int k = ks * 16 + (lane & 15);
            const int nc = (wn >> 3) + ni;
            const unsigned addr = smb + 32768 + k * 128 + ((nc ^ (k & 7)) << 4);
            asm volatile("ldmatrix.sync.aligned.m8n8.x2.trans.shared.b16 {%0,%1}, [%2];"
                : "=r"(rb[ni][0]), "=r"(rb[ni][1]) : "r"(addr));
        }
        #pragma unroll
        for (int mi = 0; mi < 2; mi++)
            #pragma unroll
            for (int ni = 0; ni < 4; ni++)
                asm volatile("mma.sync.aligned.m16n8k16.row.col.f32.f16.f16.f32 "
                    "{%0,%1,%2,%3}, {%4,%5,%6,%7}, {%8,%9}, {%0,%1,%2,%3};"
                    : "+f"(c[mi][ni][0]), "+f"(c[mi][ni][1]),
                      "+f"(c[mi][ni][2]), "+f"(c[mi][ni][3])
                    : "r"(ra[mi][0]), "r"(ra[mi][1]), "r"(ra[mi][2]), "r"(ra[mi][3]),
                      "r"(rb[ni][0]), "r"(rb[ni][1]));
    }
    __syncthreads();

    __half* Cs = (__half*)sm;
    #pragma unroll
    for (int mi = 0; mi < 2; mi++)
        #pragma unroll
        for (int ni = 0; ni < 4; ni++) {
            const int r0 = wm + mi * 16 + (lane >> 2);
            const int col = wn + ni * 8 + (lane & 3) * 2;
            __half2 lo = __floats2half2_rn(c[mi][ni][0], c[mi][ni][1]);
            __half2 hi = __floats2half2_rn(c[mi][ni][2], c[mi][ni][3]);
            *(__half2*)&Cs[r0 * 72 + col] = lo;
            *(__half2*)&Cs[(r0 + 8) * 72 + col] = hi;
        }
    __syncthreads();

    #pragma unroll
    for (int pass = 0; pass < 4; pass++) {
        const int r = pass * 32 + (tid >> 3);
        const int jc = (tid & 7) * 8;
        if (bm + r < M) {
            uint4 v = *(uint4*)&Cs[r * 72 + jc];
            *(uint4*)&g_hh[(size_t)(bm + r) * HC + bn + jc] = v;
        }
    }

    {
        const int headbase = blockIdx.y * 2;
        const int hloc = lane >> 4;
        const int cc = (lane & 15) * 2;
        const float as0 = att_src[(headbase + hloc) * CC + cc];
        const float as1 = att_src[(headbase + hloc) * CC + cc + 1];
        const float ad0 = att_dst[(headbase + hloc) * CC + cc];
        const float ad1 = att_dst[(headbase + hloc) * CC + cc + 1];
        #pragma unroll 4
        for (int rr = 0; rr < 16; rr++) {
            const int r = w * 16 + rr;
            float2 v = __half22float2(*(__half2*)&Cs[r * 72 + hloc * 32 + cc]);
            float ps = v.x * as0 + v.y * as1;
            float pd = v.x * ad0 + v.y * ad1;
            #pragma unroll
            for (int o = 1; o <= 8; o <<= 1) {
                ps += __shfl_xor_sync(0xFFFFFFFFu, ps, o);
                pd += __shfl_xor_sync(0xFFFFFFFFu, pd, o);
            }
            if ((lane & 15) == 0 && bm + r < M) {
                g_asrc[(bm + r) * HH + headbase + hloc] = ps;
                g_adst[(bm + r) * HH + headbase + hloc] = pd;
            }
        }
    }
}

// ---------------- CSR build ----------------
__global__ void degree_kernel(const void* ei, int E) {
    int e = (blockIdx.x * blockDim.x + threadIdx.x) * 2;
    if (e >= E) return;
    int is64 = g_is64;
    atomicAdd(&g_deg[edge_idx(ei, e, is64)], 1);
    if (e + 1 < E) atomicAdd(&g_deg[edge_idx(ei, e + 1, is64)], 1);
}

// ---- 3-phase parallel exclusive scan of g_deg -> g_rowptr ----
__device__ __forceinline__ int block_scan_excl(int v, int tid, int* total) {
    __shared__ int wt[8];
    const int lane = tid & 31, w = tid >> 5;
    int ic = v;
    #pragma unroll
    for (int o = 1; o < 32; o <<= 1) {
        int u = __shfl_up_sync(0xFFFFFFFFu, ic, o);
        if (lane >= o) ic += u;
    }
    if (lane == 31) wt[w] = ic;
    __syncthreads();
    if (w == 0) {
        int t = (lane < 8) ? wt[lane] : 0;
        #pragma unroll
        for (int o = 1; o < 8; o <<= 1) {
            int u = __shfl_up_sync(0xFFFFFFFFu, t, o);
            if (lane >= o) t += u;
        }
        if (lane < 8) wt[lane] = t;
    }
    __syncthreads();
    int base = (w > 0) ? wt[w - 1] : 0;
    *total = wt[7];
    return base + ic - v;
}

__global__ void scan1_kernel(int n) {
    const int idx = blockIdx.x * 256 + threadIdx.x;
    int v = (idx < n) ? g_deg[idx] : 0;
    #pragma unroll
    for (int o = 16; o > 0; o >>= 1) v += __shfl_xor_sync(0xFFFFFFFFu, v, o);
    __shared__ int wt[8];
    if ((threadIdx.x & 31) == 0) wt[threadIdx.x >> 5] = v;
    __syncthreads();
    if (threadIdx.x == 0) {
        int s = 0;
        #pragma unroll
        for (int j = 0; j < 8; j++) s += wt[j];
        g_bsum[blockIdx.x] = s;
    }
}

__global__ void scan2_kernel(int nb, int n) {
    const int tid = threadIdx.x;
    int v = (tid < nb) ? g_bsum[tid] : 0;
    int total;
    int ex = block_scan_excl(v, tid, &total);
    if (tid < nb) g_bbase[tid] = ex;
    if (tid == 0) g_rowptr[n] = total;
}

__global__ void scan3_kernel(int n) {
    const int idx = blockIdx.x * 256 + threadIdx.x;
    int v = (idx < n) ? g_deg[idx] : 0;
    int total;
    int ex = block_scan_excl(v, threadIdx.x, &total);
    if (idx < n) {
        g_rowptr[idx] = g_bbase[blockIdx.x] + ex;
        g_deg[idx] = 0;
    }
}

__global__ void scatter_kernel(const void* ei, int E) {
    int e = blockIdx.x * blockDim.x + threadIdx.x;
    if (e >= E) return;
    int is64 = g_is64;
    int d = edge_idx(ei, e, is64);
    int s = edge_idx(ei, (long long)E + e, is64);
    int pos = atomicAdd(&g_deg[d], 1);
    g_edge[g_rowptr[d] + pos] = make_int2(s, e);
}

// ---- aggregate: warp per node, 1xLDG.128 row gathers, 8-edge chunks ---------
__device__ __forceinline__ void acc_row8(float* acc, float w,
                                         const __half* row, int lane) {
    uint4 v = *(const uint4*)&row[lane * 8];    // cols lane*8..+7
    float2 f0 = __half22float2(*(__half2*)&v.x);
    float2 f1 = __half22float2(*(__half2*)&v.y);
    float2 f2 = __half22float2(*(__half2*)&v.z);
    float2 f3 = __half22float2(*(__half2*)&v.w);
    acc[0] += w * f0.x; acc[1] += w * f0.y;
    acc[2] += w * f1.x; acc[3] += w * f1.y;
    acc[4] += w * f2.x; acc[5] += w * f2.y;
    acc[6] += w * f3.x; acc[7] += w * f3.y;
}

__global__ __launch_bounds__(256)
void agg_kernel(const float* __restrict__ dp,
                const float* __restrict__ dp_self,
                const float* __restrict__ bias,
                float* __restrict__ out, int n) {
    const int i = (blockIdx.x * blockDim.x + threadIdx.x) >> 5;
    const int lane = threadIdx.x & 31;
    if (i >= n) return;
    const int hh = lane & 7;     // head for score phase
    const int eo = lane >> 3;    // edge-pair index (0..3)
    const int hg = lane >> 2;    // head owning gather cols lane*8..+7

    const float adh = g_adst[i * HH + hh];
    float a0 = g_asrc[i * HH + hh] + adh;
    a0 = a0 > 0.f ? a0 : 0.2f * a0;
    const float e0 = __expf(a0);                 // unnormalized self weight
    float sp = 0.f;                              // per-lane partial denom

    const float wself = e0 * dp_self[i * HH + hh];
    const float ws = __shfl_sync(0xFFFFFFFFu, wself, hg);
    float acc[8];
    #pragma unroll
    for (int q = 0; q < 8; q++) acc[q] = 0.f;
    acc_row8(acc, ws, &g_hh[(size_t)i * HC], lane);

    const int beg = g_rowptr[i], end = g_rowptr[i + 1];
    for (int cb = beg; cb < end; cb += 8) {
        const int sa = cb + 2 * eo, sb = sa + 1;
        int srca = i, srcb = i;
        float wma = 0.f, wmb = 0.f;
        if (sa < end) {
            int2 se = g_edge[sa];
            srca = se.x;
            float t = g_asrc[srca * HH + hh] + adh;
            t = t > 0.f ? t : 0.2f * t;
            float ew = __expf(t);
            sp += ew;
            wma = ew * dp[(size_t)se.y * HH + hh];
        }
        if (sb < end) {
            int2 se = g_edge[sb];
            srcb = se.x;
            float t = g_asrc[srcb * HH + hh] + adh;
            t = t > 0.f ? t : 0.2f * t;
            float ew = __expf(t);
            sp += ew;
            wmb = ew * dp[(size_t)se.y * HH + hh];
        }
        const int ne = min(end - cb, 8);   // warp-uniform
        if (ne == 8) {
            #pragma unroll
            for (int p = 0; p < 8; p += 2) {
                const int q8 = (p >> 1) * 8;
                int   s1 = __shfl_sync(0xFFFFFFFFu, srca, q8);
                int   s2 = __shfl_sync(0xFFFFFFFFu, srcb, q8);
                float w1 = __shfl_sync(0xFFFFFFFFu, wma, q8 + hg);
                float w2 = __shfl_sync(0xFFFFFFFFu, wmb, q8 + hg);
                acc_row8(acc, w1, &g_hh[(size_t)s1 * HC], lane);
                acc_row8(acc, w2, &g_hh[(size_t)s2 * HC], lane);
            }
        } else {
            for (int p = 0; p < ne; p++) {
                const int q8 = (p >> 1) * 8;
                int   sl = __shfl_sync(0xFFFFFFFFu, (p & 1) ? srcb : srca, q8);
                float wl = __shfl_sync(0xFFFFFFFFu, (p & 1) ? wmb : wma, q8 + hg);
                acc_row8(acc, wl, &g_hh[(size_t)sl * HC], lane);
            }
        }
    }

    // denom per head hh: e0 + sum over the 4 edge-pair lanes of this head
    sp += __shfl_xor_sync(0xFFFFFFFFu, sp, 8);
    sp += __shfl_xor_sync(0xFFFFFFFFu, sp, 16);
    const float rs = 1.f / (e0 + sp);
    const float r = __shfl_sync(0xFFFFFFFFu, rs, hg);

    const float4 b1 = ((const float4*)bias)[lane * 2];
    const float4 b2 = ((const float4*)bias)[lane * 2 + 1];
    float4* op = (float4*)&out[(size_t)i * HC + lane * 8];
    op[0] = make_float4(acc[0] * r + b1.x, acc[1] * r + b1.y,
                        acc[2] * r + b1.z, acc[3] * r + b1.w);
    op[1] = make_float4(acc[4] * r + b2.x, acc[5] * r + b2.y,
                        acc[6] * r + b2.z, acc[7] * r + b2.w);
}

// ---------------- launcher ----------------
extern "C" void kernel_launch(void* const* d_in, const int* in_sizes, int n_in,
                              void* d_out, int out_size) {
    const float* x       = (const float*)d_in[0];
    const void*  ei      = d_in[1];
    const float* dp      = (const float*)d_in[2];
    const float* dp_self = (const float*)d_in[3];
    const float* W       = (const float*)d_in[4];
    const float* att_src = (const float*)d_in[5];
    const float* att_dst = (const float*)d_in[6];
    const float* bias    = (const float*)d_in[7];
    float* out = (float*)d_out;

    int n = in_sizes[0] / FIN;   // 50000
    int E = in_sizes[2] / HH;    // 800000
    int nb = (n + 255) / 256;    // 196

    init_kernel<<<(n + 255) / 256, 256>>>(ei, n);                 // 1
    degree_kernel<<<(E / 2 + 255) / 256, 256>>>(ei, E);           // 2
    scan1_kernel<<<nb, 256>>>(n);                                 // 3
    dim3 ggrid((n + 127) / 128, HC / 64);
    gemm_kernel<<<ggrid, 256>>>(x, W, att_src, att_dst, n);       // 4 <- profiled
    scan2_kernel<<<1, 256>>>(nb, n);                              // 5
    scan3_kernel<<<nb, 256>>>(n);                                 // 6
    scatter_kernel<<<(E + 255) / 256, 256>>>(ei, E);              // 7
    agg_kernel<<<(n * 32 + 255) / 256, 256>>>(dp, dp_self, bias, out, n); // 8
}

// round 17
// speedup vs baseline: 1.3798x; 1.3798x over previous
#include <cuda_runtime.h>
#include <cuda_bf16.h>
#include <cuda_fp16.h>

#define NN 50000
#define EE 800000
#define FIN 128
#define HH 8
#define CC 32
#define HC 256
#define SCAN_NB 196            // ceil(50000/256)

__device__ __half g_hh[NN * HC];      // h in fp16 (gather payload)
__device__ float g_asrc[NN * HH];
__device__ float g_adst[NN * HH];
__device__ int   g_deg[NN];
__device__ int   g_rowptr[NN + 1];
__device__ int2  g_edge[EE];          // (src, eid) packed
__device__ int   g_bsum[SCAN_NB];
__device__ int   g_bbase[SCAN_NB];
__device__ int   g_is64;

// ---------------- init: zero degree counters + detect edge_index dtype --------
__global__ void init_kernel(const void* ei, int n) {
    int i = blockIdx.x * blockDim.x + threadIdx.x;
    if (i < n) g_deg[i] = 0;
    if (i == 0) {
        const long long* p = (const long long*)ei;
        int ok = 1;
        for (int k = 0; k < 16; k++) {
            long long v = p[k];
            if (v < 0 || v >= NN) ok = 0;
        }
        g_is64 = ok;
    }
}

__device__ __forceinline__ int edge_idx(const void* ei, long long k, int is64) {
    return is64 ? (int)((const long long*)ei)[k] : ((const int*)ei)[k];
}

// ---------- tensor-core GEMM: 128Mx64N per block, full K=128 in smem ----------
// (R13 configuration — measured 37.0us; + residency hint for 2 CTAs/SM)
__global__ __launch_bounds__(256, 2)
void gemm_kernel(const float* __restrict__ A, const float* __restrict__ B,
                 const float* __restrict__ att_src, const float* __restrict__ att_dst,
                 int M) {
    __shared__ __align__(16) unsigned char sm[49152];
    const int tid = threadIdx.x;
    const int lane = tid & 31, w = tid >> 5;
    const int bm = blockIdx.x * 128;
    const int bn = blockIdx.y * 64;

    #pragma unroll
    for (int j = 0; j < 8; j++) {
        const int ci = j * 256 + tid;
        const int m = ci >> 4, kc = ci & 15;
        uint4 v = make_uint4(0u, 0u, 0u, 0u);
        if (bm + m < M) {
            const float4 f0 = *(const float4*)&A[(size_t)(bm + m) * FIN + kc * 8];
            const float4 f1 = *(const float4*)&A[(size_t)(bm + m) * FIN + kc * 8 + 4];
            __half2 h0 = __floats2half2_rn(f0.x, f0.y);
            __half2 h1 = __floats2half2_rn(f0.z, f0.w);
            __half2 h2 = __floats2half2_rn(f1.x, f1.y);
            __half2 h3 = __floats2half2_rn(f1.z, f1.w);
            v = make_uint4(*(unsigned*)&h0, *(unsigned*)&h1,
                           *(unsigned*)&h2, *(unsigned*)&h3);
        }
        *(uint4*)&sm[m * 256 + ((kc ^ (m & 7)) << 4)] = v;
    }
    #pragma unroll
    for (int j = 0; j < 4; j++) {
        const int ci = j * 256 + tid;
        const int k = ci >> 3, nc = ci & 7;
        const float4 f0 = *(const float4*)&B[(size_t)k * HC + bn + nc * 8];
        const float4 f1 = *(const float4*)&B[(size_t)k * HC + bn + nc * 8 + 4];
        __half2 h0 = __floats2half2_rn(f0.x, f0.y);
        __half2 h1 = __floats2half2_rn(f0.z, f0.w);
        __half2 h2 = __floats2half2_rn(f1.x, f1.y);
        __half2 h3 = __floats2half2_rn(f1.z, f1.w);
        uint4 v = make_uint4(*(unsigned*)&h0, *(unsigned*)&h1,
                             *(unsigned*)&h2, *(unsigned*)&h3);
        *(uint4*)&sm[32768 + k * 128 + ((nc ^ (k & 7)) << 4)] = v;
    }
    __syncthreads();

    const int wm = (w & 3) * 32;
    const int wn = (w >> 2) * 32;
    const unsigned smb = (unsigned)__cvta_generic_to_shared(sm);

    float c[2][4][4];
    #pragma unroll
    for (int mi = 0; mi < 2; mi++)
        #pragma unroll
        for (int ni = 0; ni < 4; ni++)
            #pragma unroll
            for (int q = 0; q < 4; q++) c[mi][ni][q] = 0.f;

    #pragma unroll
    for (int ks = 0; ks < 8; ks++) {
        unsigned ra[2][4];
        #pragma unroll
        for (int mi = 0; mi < 2; mi++) {
            const int row = wm + mi * 16 + (lane & 15);
            const int kc = ks * 2 + (lane >> 4);
            const unsigned addr = smb + row * 256 + ((kc ^ (row & 7)) << 4);
            asm volatile("ldmatrix.sync.aligned.m8n8.x4.shared.b16 {%0,%1,%2,%3}, [%4];"
                : "=r"(ra[mi][0]), "=r"(ra[mi][1]), "=r"(ra[mi][2]), "=r"(ra[mi][3])
                : "r"(addr));
        }
        unsigned rb[4][2];
        #pragma unroll
        for (int ni = 0; ni < 4; ni++) {
            const int k = ks * 16 + (lane & 15);
            const int nc = (wn >> 3) + ni;
            const unsigned addr = smb + 32768 + k * 128 + ((nc ^ (k & 7)) << 4);
            asm volatile("ldmatrix.sync.aligned.m8n8.x2.trans.shared.b16 {%0,%1}, [%2];"
                : "=r"(rb[ni][0]), "=r"(rb[ni][1]) : "r"(addr));
        }
        #pragma unroll
        for (int mi = 0; mi < 2; mi++)
            #pragma unroll
            for (int ni = 0; ni < 4; ni++)
                asm volatile("mma.sync.aligned.m16n8k16.row.col.f32.f16.f16.f32 "
                    "{%0,%1,%2,%3}, {%4,%5,%6,%7}, {%8,%9}, {%0,%1,%2,%3};"
                    : "+f"(c[mi][ni][0]), "+f"(c[mi][ni][1]),
                      "+f"(c[mi][ni][2]), "+f"(c[mi][ni][3])
                    : "r"(ra[mi][0]), "r"(ra[mi][1]), "r"(ra[mi][2]), "r"(ra[mi][3]),
                      "r"(rb[ni][0]), "r"(rb[ni][1]));
    }
    __syncthreads();

    __half* Cs = (__half*)sm;
    #pragma unroll
    for (int mi = 0; mi < 2; mi++)
        #pragma unroll
        for (int ni = 0; ni < 4; ni++) {
            const int r0 = wm + mi * 16 + (lane >> 2);
            const int col = wn + ni * 8 + (lane & 3) * 2;
            __half2 lo = __floats2half2_rn(c[mi][ni][0], c[mi][ni][1]);
            __half2 hi = __floats2half2_rn(c[mi][ni][2], c[mi][ni][3]);
            *(__half2*)&Cs[r0 * 72 + col] = lo;
            *(__half2*)&Cs[(r0 + 8) * 72 + col] = hi;
        }
    __syncthreads();

    #pragma unroll
    for (int pass = 0; pass < 4; pass++) {
        const int r = pass * 32 + (tid >> 3);
        const int jc = (tid & 7) * 8;
        if (bm + r < M) {
            uint4 v = *(uint4*)&Cs[r * 72 + jc];
            *(uint4*)&g_hh[(size_t)(bm + r) * HC + bn + jc] = v;
        }
    }

    {
        const int headbase = blockIdx.y * 2;
        const int hloc = lane >> 4;
        const int cc = (lane & 15) * 2;
        const float as0 = att_src[(headbase + hloc) * CC + cc];
        const float as1 = att_src[(headbase + hloc) * CC + cc + 1];
        const float ad0 = att_dst[(headbase + hloc) * CC + cc];
        const float ad1 = att_dst[(headbase + hloc) * CC + cc + 1];
        #pragma unroll 4
        for (int rr = 0; rr < 16; rr++) {
            const int r = w * 16 + rr;
            float2 v = __half22float2(*(__half2*)&Cs[r * 72 + hloc * 32 + cc]);
            float ps = v.x * as0 + v.y * as1;
            float pd = v.x * ad0 + v.y * ad1;
            #pragma unroll
            for (int o = 1; o <= 8; o <<= 1) {
                ps += __shfl_xor_sync(0xFFFFFFFFu, ps, o);
                pd += __shfl_xor_sync(0xFFFFFFFFu, pd, o);
            }
            if ((lane & 15) == 0 && bm + r < M) {
                g_asrc[(bm + r) * HH + headbase + hloc] = ps;
                g_adst[(bm + r) * HH + headbase + hloc] = pd;
            }
        }
    }
}

// ---------------- CSR build ----------------
__global__ void degree_kernel(const void* ei, int E) {
    int e = blockIdx.x * blockDim.x + threadIdx.x;
    if (e >= E) return;
    int d = edge_idx(ei, e, g_is64);
    atomicAdd(&g_deg[d], 1);
}

// ---- 3-phase parallel exclusive scan of g_deg -> g_rowptr ----
__device__ __forceinline__ int block_scan_excl(int v, int tid, int* total) {
    __shared__ int wt[8];
    const int lane = tid & 31, w = tid >> 5;
    int ic = v;
    #pragma unroll
    for (int o = 1; o < 32; o <<= 1) {
        int u = __shfl_up_sync(0xFFFFFFFFu, ic, o);
        if (lane >= o) ic += u;
    }
    if (lane == 31) wt[w] = ic;
    __syncthreads();
    if (w == 0) {
        int t = (lane < 8) ? wt[lane] : 0;
        #pragma unroll
        for (int o = 1; o < 8; o <<= 1) {
            int u = __shfl_up_sync(0xFFFFFFFFu, t, o);
            if (lane >= o) t += u;
        }
        if (lane < 8) wt[lane] = t;
    }
    __syncthreads();
    int base = (w > 0) ? wt[w - 1] : 0;
    *total = wt[7];
    return base + ic - v;
}

__global__ void scan1_kernel(int n) {
    const int idx = blockIdx.x * 256 + threadIdx.x;
    int v = (idx < n) ? g_deg[idx] : 0;
    #pragma unroll
    for (int o = 16; o > 0; o >>= 1) v += __shfl_xor_sync(0xFFFFFFFFu, v, o);
    __shared__ int wt[8];
    if ((threadIdx.x & 31) == 0) wt[threadIdx.x >> 5] = v;
    __syncthreads();
    if (threadIdx.x == 0) {
        int s = 0;
        #pragma unroll
        for (int j = 0; j < 8; j++) s += wt[j];
        g_bsum[blockIdx.x] = s;
    }
}

__global__ void scan2_kernel(int nb, int n) {
    const int tid = threadIdx.x;
    int v = (tid < nb) ? g_bsum[tid] : 0;
    int total;
    int ex = block_scan_excl(v, tid, &total);
    if (tid < nb) g_bbase[tid] = ex;
    if (tid == 0) g_rowptr[n] = total;
}

__global__ void scan3_kernel(int n) {
    const int idx = blockIdx.x * 256 + threadIdx.x;
    int v = (idx < n) ? g_deg[idx] : 0;
    int total;
    int ex = block_scan_excl(v, threadIdx.x, &total);
    if (idx < n) {
        g_rowptr[idx] = g_bbase[blockIdx.x] + ex;
        g_deg[idx] = 0;
    }
}

__global__ void scatter_kernel(const void* ei, int E) {
    int e = blockIdx.x * blockDim.x + threadIdx.x;
    if (e >= E) return;
    int is64 = g_is64;
    int d = edge_idx(ei, e, is64);
    int s = edge_idx(ei, (long long)E + e, is64);
    int pos = atomicAdd(&g_deg[d], 1);
    g_edge[g_rowptr[d] + pos] = make_int2(s, e);
}

// ---- single-pass softmax-free aggregate (R13 version — measured best) -------
__device__ __forceinline__ void acc_halfrow(float4& acc1, float4& acc2,
                                            float w1, float w2,
                                            const uint2* hr, int lane) {
    uint2 r1 = hr[lane];        // cols lane*4..+3
    uint2 r2 = hr[32 + lane];   // cols 128+lane*4..+3
    float2 a0 = __half22float2(*(__half2*)&r1.x);
    float2 a1 = __half22float2(*(__half2*)&r1.y);
    float2 b0 = __half22float2(*(__half2*)&r2.x);
    float2 b1 = __half22float2(*(__half2*)&r2.y);
    acc1.x += w1 * a0.x; acc1.y += w1 * a0.y;
    acc1.z += w1 * a1.x; acc1.w += w1 * a1.y;
    acc2.x += w2 * b0.x; acc2.y += w2 * b0.y;
    acc2.z += w2 * b1.x; acc2.w += w2 * b1.y;
}

__global__ __launch_bounds__(256)
void agg_kernel(const float* __restrict__ dp,
                const float* __restrict__ dp_self,
                const float* __restrict__ bias,
                float* __restrict__ out, int n) {
    const int i = (blockIdx.x * blockDim.x + threadIdx.x) >> 5;
    const int lane = threadIdx.x & 31;
    if (i >= n) return;
    const int hh = lane & 7;
    const int eo = lane >> 3;
    const int hq = lane >> 3;

    const float adh = g_adst[i * HH + hh];
    float a0 = g_asrc[i * HH + hh] + adh;
    a0 = a0 > 0.f ? a0 : 0.2f * a0;
    const float e0 = __expf(a0);                 // unnormalized self weight
    float sp = 0.f;                              // per-lane partial denom

    const float wself = e0 * dp_self[i * HH + hh];
    const float ws1 = __shfl_sync(0xFFFFFFFFu, wself, hq);
    const float ws2 = __shfl_sync(0xFFFFFFFFu, wself, 4 + hq);
    float4 acc1 = make_float4(0.f, 0.f, 0.f, 0.f);
    float4 acc2 = make_float4(0.f, 0.f, 0.f, 0.f);
    acc_halfrow(acc1, acc2, ws1, ws2, (const uint2*)&g_hh[(size_t)i * HC], lane);

    const int beg = g_rowptr[i], end = g_rowptr[i + 1];
    for (int cb = beg; cb < end; cb += 4) {
        const int slot = cb + eo;
        float wm = 0.f;
        int src = i;
        if (slot < end) {
            int2 se = g_edge[slot];
            src = se.x;
            float t = g_asrc[src * HH + hh] + adh;
            t = t > 0.f ? t : 0.2f * t;
            float ew = __expf(t);
            sp += ew;                            // deferred reduction
            wm = ew * dp[(size_t)se.y * HH + hh];
        }
        const int ne = min(end - cb, 4);
        if (ne == 4) {
            #pragma unroll
            for (int e2 = 0; e2 < 4; e2++) {
                int   se = __shfl_sync(0xFFFFFFFFu, src, e2 * 8);
                float w1 = __shfl_sync(0xFFFFFFFFu, wm, e2 * 8 + hq);
                float w2 = __shfl_sync(0xFFFFFFFFu, wm, e2 * 8 + 4 + hq);
                acc_halfrow(acc1, acc2, w1, w2, (const uint2*)&g_hh[(size_t)se * HC], lane);
            }
        } else {
            for (int e2 = 0; e2 < ne; e2++) {
                int   se = __shfl_sync(0xFFFFFFFFu, src, e2 * 8);
                float w1 = __shfl_sync(0xFFFFFFFFu, wm, e2 * 8 + hq);
                float w2 = __shfl_sync(0xFFFFFFFFu, wm, e2 * 8 + 4 + hq);
                acc_halfrow(acc1, acc2, w1, w2, (const uint2*)&g_hh[(size_t)se * HC], lane);
            }
        }
    }

    sp += __shfl_xor_sync(0xFFFFFFFFu, sp, 8);
    sp += __shfl_xor_sync(0xFFFFFFFFu, sp, 16);
    const float rs = 1.f / (e0 + sp);
    const float r1 = __shfl_sync(0xFFFFFFFFu, rs, hq);
    const float r2 = __shfl_sync(0xFFFFFFFFu, rs, 4 + hq);
    const float4 b1 = ((const float4*)bias)[lane];
    const float4 b2 = ((const float4*)bias)[32 + lane];
    float4* orow = (float4*)&out[(size_t)i * HC];
    orow[lane]      = make_float4(acc1.x * r1 + b1.x, acc1.y * r1 + b1.y,
                                  acc1.z * r1 + b1.z, acc1.w * r1 + b1.w);
    orow[32 + lane] = make_float4(acc2.x * r2 + b2.x, acc2.y * r2 + b2.y,
                                  acc2.z * r2 + b2.z, acc2.w * r2 + b2.w);
}

// ---------------- launcher ----------------
extern "C" void kernel_launch(void* const* d_in, const int* in_sizes, int n_in,
                              void* d_out, int out_size) {
    const float* x       = (const float*)d_in[0];
    const void*  ei      = d_in[1];
    const float* dp      = (const float*)d_in[2];
    const float* dp_self = (const float*)d_in[3];
    const float* W       = (const float*)d_in[4];
    const float* att_src = (const float*)d_in[5];
    const float* att_dst = (const float*)d_in[6];
    const float* bias    = (const float*)d_in[7];
    float* out = (float*)d_out;

    int n = in_sizes[0] / FIN;   // 50000
    int E = in_sizes[2] / HH;    // 800000
    int nb = (n + 255) / 256;    // 196

    init_kernel<<<(n + 255) / 256, 256>>>(ei, n);                 // 1
    degree_kernel<<<(E + 255) / 256, 256>>>(ei, E);               // 2
    scan1_kernel<<<nb, 256>>>(n);                                 // 3
    dim3 ggrid((n + 127) / 128, HC / 64);
    gemm_kernel<<<ggrid, 256>>>(x, W, att_src, att_dst, n);       // 4 <- profiled
    scan2_kernel<<<1, 256>>>(nb, n);                              // 5
    scan3_kernel<<<1 + (n - 1) / 256, 256>>>(n);                  // 6
    scatter_kernel<<<(E + 255) / 256, 256>>>(ei, E);              // 7
    agg_kernel<<<(n * 32 + 255) / 256, 256>>>(dp, dp_self, bias, out, n); // 8
}